// round 2
// baseline (speedup 1.0000x reference)
#include <cuda_runtime.h>
#include <math.h>

// Problem constants
#define BATCH 128
#define NN    50          // N (permutation size)
#define FDIM  1024
#define HDIM  4096
#define MROWS (BATCH*NN)  // 6400

// Output layout (floats)
#define PSI_OFF  0
#define PERM_OFF (BATCH*NN*NN)        // 320000
#define X_OFF    (2*BATCH*NN*NN)      // 640000
#define DIST_OFF (3*BATCH*NN*NN)      // 960000

// Scratch (device globals: allocation-free rule)
__device__ float g_h[(size_t)MROWS * HDIM];   // hidden activations, ~105 MB
__device__ float g_P[BATCH * NN * NN];        // psi workspace

// ---------------------------------------------------------------------------
// Kernel 1: C = leaky_relu(x @ W1 + b1)
// M=6400, N=4096, K=1024. Classic 128x128x16 SGEMM, 8x8 per thread, 256 thr.
// ---------------------------------------------------------------------------
#define BM 128
#define BN 128
#define BK 16
#define TM 8
#define TN 8

__global__ __launch_bounds__(256) void gemm1_kernel(
    const float* __restrict__ A,     // [6400,1024]
    const float* __restrict__ W,     // [1024,4096]
    const float* __restrict__ bias,  // [4096]
    float* __restrict__ C)           // [6400,4096]
{
    __shared__ float As[BK][BM];
    __shared__ float Bs[BK][BN];

    const int bx = blockIdx.x;   // N tile: 0..31
    const int by = blockIdx.y;   // M tile: 0..49
    const int tid = threadIdx.x;
    const int tx = tid & 15;
    const int ty = tid >> 4;

    const float* Ab = A + (size_t)by * BM * FDIM;
    const float* Wb = W + (size_t)bx * BN;

    float acc[TM][TN];
#pragma unroll
    for (int i = 0; i < TM; i++)
#pragma unroll
        for (int j = 0; j < TN; j++) acc[i][j] = 0.f;

    const int arow = tid >> 2;          // 0..63
    const int acol = (tid & 3) * 4;     // 0,4,8,12
    const int brow = tid >> 5;          // 0..7
    const int bcol = (tid & 31) * 4;    // 0..124

    for (int k0 = 0; k0 < FDIM; k0 += BK) {
        float4 a0 = *(const float4*)(Ab + (size_t)arow * FDIM + k0 + acol);
        float4 a1 = *(const float4*)(Ab + (size_t)(arow + 64) * FDIM + k0 + acol);
        As[acol + 0][arow] = a0.x;  As[acol + 1][arow] = a0.y;
        As[acol + 2][arow] = a0.z;  As[acol + 3][arow] = a0.w;
        As[acol + 0][arow + 64] = a1.x;  As[acol + 1][arow + 64] = a1.y;
        As[acol + 2][arow + 64] = a1.z;  As[acol + 3][arow + 64] = a1.w;

        float4 b0 = *(const float4*)(Wb + (size_t)(k0 + brow) * HDIM + bcol);
        float4 b1 = *(const float4*)(Wb + (size_t)(k0 + brow + 8) * HDIM + bcol);
        *(float4*)&Bs[brow][bcol]     = b0;
        *(float4*)&Bs[brow + 8][bcol] = b1;

        __syncthreads();

#pragma unroll
        for (int k = 0; k < BK; k++) {
            float ar[TM], br[TN];
            float4 av0 = *(const float4*)&As[k][ty * TM];
            float4 av1 = *(const float4*)&As[k][ty * TM + 4];
            ar[0]=av0.x; ar[1]=av0.y; ar[2]=av0.z; ar[3]=av0.w;
            ar[4]=av1.x; ar[5]=av1.y; ar[6]=av1.z; ar[7]=av1.w;
            float4 bv0 = *(const float4*)&Bs[k][tx * TN];
            float4 bv1 = *(const float4*)&Bs[k][tx * TN + 4];
            br[0]=bv0.x; br[1]=bv0.y; br[2]=bv0.z; br[3]=bv0.w;
            br[4]=bv1.x; br[5]=bv1.y; br[6]=bv1.z; br[7]=bv1.w;
#pragma unroll
            for (int i = 0; i < TM; i++)
#pragma unroll
                for (int j = 0; j < TN; j++)
                    acc[i][j] = fmaf(ar[i], br[j], acc[i][j]);
        }
        __syncthreads();
    }

#pragma unroll
    for (int i = 0; i < TM; i++) {
        int gm = by * BM + ty * TM + i;
#pragma unroll
        for (int j = 0; j < TN; j++) {
            int gn = bx * BN + tx * TN + j;
            float c = acc[i][j] + bias[gn];
            c = (c > 0.f) ? c : 0.01f * c;   // leaky_relu, slope 0.01
            C[(size_t)gm * HDIM + gn] = c;
        }
    }
}

// ---------------------------------------------------------------------------
// Kernel 2: P = exp(leaky_relu(h @ W2 + b2))   [6400 rows, 50 cols]
// ---------------------------------------------------------------------------
__global__ __launch_bounds__(256) void gemm2_kernel(
    const float* __restrict__ h,    // [6400,4096]
    const float* __restrict__ W2,   // [4096,50]
    const float* __restrict__ b2,   // [50]
    float* __restrict__ P)          // [128,50,50] flattened rows
{
    __shared__ float sh[HDIM];
    __shared__ float red[4][64];

    const int r = blockIdx.x;
    const int tid = threadIdx.x;
    const float* hr = h + (size_t)r * HDIM;

    for (int k = tid; k < HDIM; k += 256) sh[k] = hr[k];
    __syncthreads();

    const int nx = tid & 63;
    const int ky = tid >> 6;

    float a0 = 0.f, a1 = 0.f, a2 = 0.f, a3 = 0.f;
    if (nx < NN) {
        const float* wcol = W2 + nx;
        const int kbase = ky * 1024;
#pragma unroll 4
        for (int k = kbase; k < kbase + 1024; k += 4) {
            a0 = fmaf(sh[k + 0], wcol[(k + 0) * NN], a0);
            a1 = fmaf(sh[k + 1], wcol[(k + 1) * NN], a1);
            a2 = fmaf(sh[k + 2], wcol[(k + 2) * NN], a2);
            a3 = fmaf(sh[k + 3], wcol[(k + 3) * NN], a3);
        }
    }
    red[ky][nx] = (a0 + a1) + (a2 + a3);
    __syncthreads();

    if (tid < NN) {
        float s = red[0][tid] + red[1][tid] + red[2][tid] + red[3][tid] + b2[tid];
        s = (s > 0.f) ? s : 0.01f * s;
        P[(size_t)r * NN + tid] = expf(s);   // TAU = 1
    }
}

// ---------------------------------------------------------------------------
// Kernel 3: Sinkhorn (5 iters), per batch. X == psi since ALPHA=1.0.
// ---------------------------------------------------------------------------
__global__ __launch_bounds__(256) void sinkhorn_kernel(
    float* __restrict__ P, float* __restrict__ out)
{
    __shared__ float sp[NN * NN];
    const int b = blockIdx.x;
    const int tid = threadIdx.x;
    float* Pb = P + (size_t)b * NN * NN;

    for (int i = tid; i < NN * NN; i += 256) sp[i] = Pb[i];
    __syncthreads();

    const int warp = tid >> 5, lane = tid & 31;

    for (int it = 0; it < 5; it++) {
        // normalize rows (sum over axis=2)
        for (int i = warp; i < NN; i += 8) {
            float v0 = sp[i * NN + lane];
            float v1 = (lane + 32 < NN) ? sp[i * NN + lane + 32] : 0.f;
            float s = v0 + v1;
#pragma unroll
            for (int o = 16; o; o >>= 1) s += __shfl_xor_sync(~0u, s, o);
            sp[i * NN + lane] = v0 / s;
            if (lane + 32 < NN) sp[i * NN + lane + 32] = v1 / s;
        }
        __syncthreads();
        // normalize cols (sum over axis=1)
        for (int j = warp; j < NN; j += 8) {
            float v0 = sp[lane * NN + j];
            float v1 = (lane + 32 < NN) ? sp[(lane + 32) * NN + j] : 0.f;
            float s = v0 + v1;
#pragma unroll
            for (int o = 16; o; o >>= 1) s += __shfl_xor_sync(~0u, s, o);
            sp[lane * NN + j] = v0 / s;
            if (lane + 32 < NN) sp[(lane + 32) * NN + j] = v1 / s;
        }
        __syncthreads();
    }

    float* psi_out = out + PSI_OFF + (size_t)b * NN * NN;
    float* x_out   = out + X_OFF   + (size_t)b * NN * NN;
    for (int i = tid; i < NN * NN; i += 256) {
        float v = sp[i];
        Pb[i] = v;
        psi_out[i] = v;
        x_out[i] = v;   // X = (1-1)*perms + 1*psi = psi exactly
    }
}

// ---------------------------------------------------------------------------
// Kernel 4: replicate the reference's BUGGY Hungarian exactly.
// Key insight: the reference never writes `minv` back (mv is a dead copy),
// so it degenerates to a greedy chain walk:
//   - from current j0: mark used; i0 = p[j0]
//   - cur[j] = cost[i0-1,j-1] - u[i0] - v[j] over FREE j
//   - j1 = argmin (lowest-index ties, like np.argmin); delta = cur[j1]
//   - way[j1] = j0  (reference sets way for all free j each iter; only the
//     chain entries are ever read, and those equal "j0 at selection time")
//   - u[p[j]] += delta, v[j] -= delta for ALL used j (incl. j=0)
//   - hop to j1; stop when p[j1]==0; rotate matching along chain.
// float64 arithmetic to match numpy's promotion bit-for-bit.
// One warp per batch. Writes perms + dist.
// ---------------------------------------------------------------------------
__global__ __launch_bounds__(32) void hungarian_kernel(
    const float* __restrict__ P,   // psi [128,50,50]
    float* __restrict__ out)
{
    __shared__ float  sc[NN * NN];           // psi (cost = -psi)
    __shared__ double u[NN + 1], v[NN + 1];
    __shared__ int    p[NN + 1], way[NN + 1];
    __shared__ int    used[NN + 1];
    __shared__ int    s_j0;
    __shared__ int    rtc[NN];

    const int b = blockIdx.x;
    const int lane = threadIdx.x;
    const double INF = 1e18;
    const float* Pb = P + (size_t)b * NN * NN;

    for (int i = lane; i < NN * NN; i += 32) sc[i] = Pb[i];
    for (int j = lane; j <= NN; j += 32) { u[j] = 0.0; v[j] = 0.0; p[j] = 0; }
    __syncwarp();

    for (int i = 1; i <= NN; i++) {
        if (lane == 0) { p[0] = i; s_j0 = 0; }
        for (int j = lane; j <= NN; j += 32) used[j] = 0;
        __syncwarp();

        while (true) {
            const int j0 = s_j0;
            if (lane == 0) used[j0] = 1;
            __syncwarp();

            const int i0 = p[j0];
            const double du = u[i0];

            double best = INF;
            int bestj = NN + 1;

            int jj = lane + 1;                       // 1..32
            if (!used[jj]) {
                double cur = -(double)sc[(i0 - 1) * NN + (jj - 1)] - du - v[jj];
                best = cur; bestj = jj;
            }
            jj = lane + 33;                          // 33..50 (lane < 18)
            if (jj <= NN && !used[jj]) {
                double cur = -(double)sc[(i0 - 1) * NN + (jj - 1)] - du - v[jj];
                if (cur < best) { best = cur; bestj = jj; }  // strict: prefer lower j
            }

            // warp argmin, lowest-index tie-break (matches np.argmin)
#pragma unroll
            for (int o = 16; o; o >>= 1) {
                double ob = __shfl_xor_sync(~0u, best, o);
                int    oj = __shfl_xor_sync(~0u, bestj, o);
                if (ob < best || (ob == best && oj < bestj)) { best = ob; bestj = oj; }
            }
            const double delta = best;
            const int j1 = bestj;
            __syncwarp();   // all reads of u/v done before updates

            // u[p[used]] += delta; v[used] -= delta  (j in 0..NN)
            int ja = lane;
            if (used[ja]) { u[p[ja]] += delta; v[ja] -= delta; }
            ja = lane + 32;
            if (ja <= NN && used[ja]) { u[p[ja]] += delta; v[ja] -= delta; }
            __syncwarp();

            if (lane == 0) { way[j1] = j0; s_j0 = j1; }
            __syncwarp();
            if (p[j1] == 0) break;
        }

        // rotate matching along the visit chain (serial, tiny)
        if (lane == 0) {
            int j0 = s_j0;
            while (j0) { int jn = way[j0]; p[j0] = p[jn]; j0 = jn; }
        }
        __syncwarp();
    }

    // row_to_col
    {
        int j = lane + 1;
        if (p[j] > 0) rtc[p[j] - 1] = j - 1;
        j = lane + 33;
        if (j <= NN && p[j] > 0) rtc[p[j] - 1] = j - 1;
    }
    __syncwarp();

    // perms (zero then one-hot) and dist
    float* pb = out + PERM_OFF + (size_t)b * NN * NN;
    for (int i = lane; i < NN * NN; i += 32) pb[i] = 0.f;
    __syncwarp();
    if (lane == 0) {
        float dsum = 0.f;
        for (int r = 0; r < NN; r++) {
            int cidx = rtc[r];
            pb[r * NN + cidx] = 1.0f;
            dsum += sc[r * NN + cidx];
        }
        out[DIST_OFF + b] = dsum / (float)NN;
    }
}

// ---------------------------------------------------------------------------
extern "C" void kernel_launch(void* const* d_in, const int* in_sizes, int n_in,
                              void* d_out, int out_size)
{
    (void)in_sizes; (void)n_in; (void)out_size;
    const float* x  = (const float*)d_in[0];
    const float* W1 = (const float*)d_in[1];
    const float* b1 = (const float*)d_in[2];
    const float* W2 = (const float*)d_in[3];
    const float* b2 = (const float*)d_in[4];
    float* out = (float*)d_out;

    float* h;  cudaGetSymbolAddress((void**)&h,  g_h);
    float* P;  cudaGetSymbolAddress((void**)&P,  g_P);

    dim3 g1(HDIM / BN, MROWS / BM);          // 32 x 50
    gemm1_kernel<<<g1, 256>>>(x, W1, b1, h);
    gemm2_kernel<<<MROWS, 256>>>(h, W2, b2, P);
    sinkhorn_kernel<<<BATCH, 256>>>(P, out);
    hungarian_kernel<<<BATCH, 32>>>(P, out);
}